// round 3
// baseline (speedup 1.0000x reference)
#include <cuda_runtime.h>
#include <cuda_bf16.h>

#define NN 10000   // nodes
#define D  128     // d_model
#define KK 16      // d_state
#define S  5       // seq len
#define NS 4       // S-1
#define EE 320000  // edges
#define PP 80000   // edges per step
#define LN_EPS 1e-5f

// ---------------- device scratch (static, no allocation) ----------------
__device__ float g_WdT[D * D];      // W_delta transposed: [out_d][j]
__device__ float g_WgT[D * D];      // W_g transposed
__device__ float g_WoT[D * D];      // W_out transposed
__device__ float g_Acont[D * KK];   // -exp(log_A)
__device__ int   g_cnt[NN * NS];
__device__ int   g_off[NN * NS + 1];
__device__ int   g_cur[NN * NS];
__device__ int   g_csr[EE];         // packed: src | (etype<<16)

// ---------------- helpers ----------------
__device__ __forceinline__ float softplus_f(float v) {
    return (v > 20.f) ? v : log1pf(__expf(v));
}

// ---------------- prep: transpose weights, precompute A_cont ----------------
__global__ void prep_kernel(const float* __restrict__ Wd,
                            const float* __restrict__ Wg,
                            const float* __restrict__ Wo,
                            const float* __restrict__ logA) {
    int i = blockIdx.x * blockDim.x + threadIdx.x;
    if (i < D * D) {
        int j = i / D;   // input row
        int d = i % D;   // output col
        g_WdT[d * D + j] = Wd[i];
        g_WgT[d * D + j] = Wg[i];
        g_WoT[d * D + j] = Wo[i];
    }
    if (i < D * KK) {
        g_Acont[i] = -expf(logA[i]);
    }
}

// ---------------- zero counters ----------------
__global__ void zero_kernel() {
    int i = blockIdx.x * blockDim.x + threadIdx.x;
    if (i < NN * NS) { g_cnt[i] = 0; g_cur[i] = 0; }
}

// ---------------- count edges per (dst, step) ----------------
__global__ void count_kernel(const int* __restrict__ perms,
                             const int* __restrict__ edge_index) {
    int i = blockIdx.x * blockDim.x + threadIdx.x;
    if (i >= NS * PP) return;
    int s = i / PP;
    int e = perms[i];
    int dst = edge_index[EE + e];
    atomicAdd(&g_cnt[dst * NS + s], 1);
}

// ---------------- single-block exclusive prefix scan over 40000 counters ----------------
__global__ void scan_kernel() {
    const int M = NN * NS;
    __shared__ int warp_sums[32];
    __shared__ int s_carry;
    int tid = threadIdx.x;          // 1024 threads
    int lane = tid & 31, wid = tid >> 5;
    if (tid == 0) s_carry = 0;
    __syncthreads();
    for (int base = 0; base < M; base += 1024) {
        int i = base + tid;
        int v = (i < M) ? g_cnt[i] : 0;
        int incl = v;
        #pragma unroll
        for (int o = 1; o < 32; o <<= 1) {
            int t = __shfl_up_sync(0xffffffffu, incl, o);
            if (lane >= o) incl += t;
        }
        if (lane == 31) warp_sums[wid] = incl;
        __syncthreads();
        int wsum = 0;
        for (int w = 0; w < wid; w++) wsum += warp_sums[w];
        int total = 0;
        #pragma unroll
        for (int w = 0; w < 32; w++) total += warp_sums[w];
        int carry = s_carry;
        if (i < M) g_off[i] = carry + wsum + (incl - v);
        __syncthreads();
        if (tid == 0) s_carry = carry + total;
        __syncthreads();
    }
    if (tid == 0) g_off[M] = s_carry;
}

// ---------------- fill CSR ----------------
__global__ void fill_kernel(const int* __restrict__ perms,
                            const int* __restrict__ edge_index,
                            const int* __restrict__ edge_type) {
    int i = blockIdx.x * blockDim.x + threadIdx.x;
    if (i >= NS * PP) return;
    int s = i / PP;
    int e = perms[i];
    int src = edge_index[e];
    int dst = edge_index[EE + e];
    int et  = edge_type[e];
    int idx = dst * NS + s;
    int pos = atomicAdd(&g_cur[idx], 1);
    g_csr[g_off[idx] + pos] = src | (et << 16);
}

// ---------------- mega kernel: one block per node ----------------
__global__ __launch_bounds__(128) void mega_kernel(
    const float* __restrict__ x,
    const float* __restrict__ rel,
    const float* __restrict__ W_B,
    const float* __restrict__ W_C,
    const float* __restrict__ b_delta,
    const float* __restrict__ b_g,
    const float* __restrict__ b_out,
    const float* __restrict__ ln_g,
    const float* __restrict__ ln_b,
    float* __restrict__ out)
{
    int n = blockIdx.x;
    int d = threadIdx.x;                  // channel, 0..127
    int lane = d & 31, warp = d >> 5;

    __shared__ __align__(16) float tok[S][D];
    __shared__ float BC[2][S][KK];        // [0]=B, [1]=C per (s,k)
    __shared__ float part[2][KK][4][S];
    __shared__ __align__(16) float scn[D];
    __shared__ float rs1[4], rs2[4];

    // ---- token 0 = x[n], tokens 1..4 = gather-mean over CSR edges ----
    float xv = x[n * D + d];
    tok[0][d] = xv;
    #pragma unroll
    for (int s = 0; s < NS; s++) {
        int idx = n * NS + s;
        int b = g_off[idx], e2 = g_off[idx + 1];
        float acc = 0.f;
        for (int t = b; t < e2; t++) {
            int pk = g_csr[t];
            int src = pk & 0xFFFF;
            int et  = pk >> 16;
            acc += x[src * D + d] + rel[et * D + d];
        }
        int cnt = e2 - b;
        tok[1 + s][d] = acc / (float)(cnt > 1 ? cnt : 1);
    }
    __syncthreads();

    // ---- delta GEMV: dl[s] = softplus(tok[s] . Wdelta[:,d] + b_delta[d]) ----
    float dl[S];
    {
        float bd = b_delta[d];
        float acc[S];
        #pragma unroll
        for (int s = 0; s < S; s++) acc[s] = bd;
        const float4* wrow = (const float4*)(g_WdT + d * D);
        #pragma unroll 8
        for (int j4 = 0; j4 < 32; j4++) {
            float4 w = wrow[j4];
            #pragma unroll
            for (int s = 0; s < S; s++) {
                float4 t4 = *(const float4*)&tok[s][4 * j4];
                acc[s] += t4.x * w.x + t4.y * w.y + t4.z * w.z + t4.w * w.w;
            }
        }
        #pragma unroll
        for (int s = 0; s < S; s++) dl[s] = softplus_f(acc[s]);
    }

    // ---- B/C GEMVs: 128 threads -> (mat:2, k:16, q:4 quarter of j-range) ----
    {
        int mat = d >> 6;
        int k   = (d >> 2) & 15;
        int q   = d & 3;
        const float* W = mat ? W_C : W_B;
        float acc[S] = {0.f, 0.f, 0.f, 0.f, 0.f};
        int j0 = q * 32;
        for (int j = j0; j < j0 + 32; j++) {
            float w = W[j * KK + k];
            #pragma unroll
            for (int s = 0; s < S; s++) acc[s] += tok[s][j] * w;
        }
        #pragma unroll
        for (int s = 0; s < S; s++) part[mat][k][q][s] = acc[s];
    }
    __syncthreads();
    if (d < 2 * KK) {
        int mat = d >> 4, k = d & 15;
        #pragma unroll
        for (int s = 0; s < S; s++)
            BC[mat][s][k] = part[mat][k][0][s] + part[mat][k][1][s]
                          + part[mat][k][2][s] + part[mat][k][3][s];
    }
    __syncthreads();

    // ---- bidirectional selective scan (per-thread channel d) ----
    float A[KK];
    {
        const float4* ar = (const float4*)(g_Acont + d * KK);
        #pragma unroll
        for (int k4 = 0; k4 < 4; k4++) {
            float4 a4 = ar[k4];
            A[4 * k4 + 0] = a4.x; A[4 * k4 + 1] = a4.y;
            A[4 * k4 + 2] = a4.z; A[4 * k4 + 3] = a4.w;
        }
    }
    float xtok[S];
    #pragma unroll
    for (int s = 0; s < S; s++) xtok[s] = tok[s][d];

    float ysum = 0.f;
    {   // forward
        float st[KK];
        #pragma unroll
        for (int k = 0; k < KK; k++) st[k] = 0.f;
        #pragma unroll
        for (int s = 0; s < S; s++) {
            float dls = dl[s];
            float dx  = dls * xtok[s];
            #pragma unroll
            for (int k = 0; k < KK; k++) {
                float a = __expf(dls * A[k]);
                st[k] = a * st[k] + dx * BC[0][s][k];
                ysum += st[k] * BC[1][s][k];
            }
        }
    }
    {   // backward (reversed token order; per-token params identical)
        float st[KK];
        #pragma unroll
        for (int k = 0; k < KK; k++) st[k] = 0.f;
        #pragma unroll
        for (int s = S - 1; s >= 0; s--) {
            float dls = dl[s];
            float dx  = dls * xtok[s];
            #pragma unroll
            for (int k = 0; k < KK; k++) {
                float a = __expf(dls * A[k]);
                st[k] = a * st[k] + dx * BC[0][s][k];
                ysum += st[k] * BC[1][s][k];
            }
        }
    }
    scn[d] = ysum * (1.f / (float)S);
    __syncthreads();

    // ---- gate & out GEMVs + residual ----
    float ga = b_g[d], oa = b_out[d];
    {
        const float4* wg = (const float4*)(g_WgT + d * D);
        const float4* wo = (const float4*)(g_WoT + d * D);
        #pragma unroll 8
        for (int j4 = 0; j4 < 32; j4++) {
            float4 g4 = wg[j4];
            float4 o4 = wo[j4];
            float4 x4 = *(const float4*)&tok[0][4 * j4];
            float4 s4 = *(const float4*)&scn[4 * j4];
            ga += x4.x * g4.x + x4.y * g4.y + x4.z * g4.z + x4.w * g4.w;
            oa += s4.x * o4.x + s4.y * o4.y + s4.z * o4.z + s4.w * o4.w;
        }
    }
    float gate = ga / (1.f + __expf(-ga));   // silu
    float res  = xv + gate * oa;

    // ---- layernorm over the 128 channels ----
    float s1 = res, s2 = res * res;
    #pragma unroll
    for (int o = 16; o > 0; o >>= 1) {
        s1 += __shfl_xor_sync(0xffffffffu, s1, o);
        s2 += __shfl_xor_sync(0xffffffffu, s2, o);
    }
    if (lane == 0) { rs1[warp] = s1; rs2[warp] = s2; }
    __syncthreads();
    float t1 = rs1[0] + rs1[1] + rs1[2] + rs1[3];
    float t2 = rs2[0] + rs2[1] + rs2[2] + rs2[3];
    float mu  = t1 * (1.f / (float)D);
    float var = t2 * (1.f / (float)D) - mu * mu;
    float inv = rsqrtf(var + LN_EPS);
    out[n * D + d] = (res - mu) * inv * ln_g[d] + ln_b[d];
}

// ---------------- launch ----------------
extern "C" void kernel_launch(void* const* d_in, const int* in_sizes, int n_in,
                              void* d_out, int out_size) {
    const float* x         = (const float*)d_in[0];
    const int*   edge_index= (const int*)  d_in[1];
    const int*   edge_type = (const int*)  d_in[2];
    const int*   perms     = (const int*)  d_in[3];
    const float* rel       = (const float*)d_in[4];
    const float* logA      = (const float*)d_in[5];
    const float* W_B       = (const float*)d_in[6];
    const float* W_C       = (const float*)d_in[7];
    const float* W_delta   = (const float*)d_in[8];
    const float* b_delta   = (const float*)d_in[9];
    const float* W_g       = (const float*)d_in[10];
    const float* b_g       = (const float*)d_in[11];
    const float* W_out     = (const float*)d_in[12];
    const float* b_out     = (const float*)d_in[13];
    const float* ln_g      = (const float*)d_in[14];
    const float* ln_b      = (const float*)d_in[15];
    float* out = (float*)d_out;

    prep_kernel<<<(D * D + 255) / 256, 256>>>(W_delta, W_g, W_out, logA);
    zero_kernel<<<(NN * NS + 255) / 256, 256>>>();
    count_kernel<<<(NS * PP + 255) / 256, 256>>>(perms, edge_index);
    scan_kernel<<<1, 1024>>>();
    fill_kernel<<<(NS * PP + 255) / 256, 256>>>(perms, edge_index, edge_type);
    mega_kernel<<<NN, 128>>>(x, rel, W_B, W_C, b_delta, b_g, b_out,
                             ln_g, ln_b, out);
}

// round 5
// speedup vs baseline: 1.0245x; 1.0245x over previous
#include <cuda_runtime.h>
#include <cuda_bf16.h>

#define NN 10000   // nodes
#define D  128     // d_model
#define KK 16      // d_state
#define S  5       // seq len
#define NS 4       // S-1
#define EE 320000  // edges
#define PP 80000   // edges per step
#define LN_EPS 1e-5f
#define M_CNT (NN * NS)          // 40000 counters
#define SCAN_BLKS 40             // ceil(40001 / 1024)

// ---------------- device scratch (static, no allocation) ----------------
__device__ float g_WdT[D * D];      // W_delta transposed: [out_d][j]
__device__ float g_WgT[D * D];      // W_g transposed
__device__ float g_WoT[D * D];      // W_out transposed
__device__ float g_Acont[D * KK];   // -exp(log_A)
__device__ int   g_cnt[M_CNT];
__device__ int   g_off[M_CNT + 1];  // within-scan-block exclusive prefix
__device__ int   g_bsum[SCAN_BLKS]; // per-scan-block totals
__device__ int   g_bbase[SCAN_BLKS + 1]; // exclusive scan of totals
__device__ int   g_cur[M_CNT];
__device__ int   g_csr[EE];         // packed: src | (etype<<16)

// ---------------- helpers ----------------
__device__ __forceinline__ float softplus_f(float v) {
    return (v > 20.f) ? v : log1pf(__expf(v));
}

// ---------------- prep: transpose weights, A_cont, zero counters ----------------
__global__ void prep_zero_kernel(const float* __restrict__ Wd,
                                 const float* __restrict__ Wg,
                                 const float* __restrict__ Wo,
                                 const float* __restrict__ logA) {
    int i = blockIdx.x * blockDim.x + threadIdx.x;
    if (i < D * D) {
        int j = i / D;   // input row
        int d = i % D;   // output col
        g_WdT[d * D + j] = Wd[i];
        g_WgT[d * D + j] = Wg[i];
        g_WoT[d * D + j] = Wo[i];
    }
    if (i < D * KK) {
        g_Acont[i] = -expf(logA[i]);
    }
    if (i < M_CNT) { g_cnt[i] = 0; g_cur[i] = 0; }
}

// ---------------- count edges per (dst, step) ----------------
__global__ void count_kernel(const int* __restrict__ perms,
                             const int* __restrict__ edge_index) {
    int i = blockIdx.x * blockDim.x + threadIdx.x;
    if (i >= NS * PP) return;
    int s = i / PP;
    int e = perms[i];
    int dst = edge_index[EE + e];
    atomicAdd(&g_cnt[dst * NS + s], 1);
}

// ---------------- hierarchical scan, phase A: per-block scan + totals ----------------
__global__ __launch_bounds__(1024) void scanA_kernel() {
    __shared__ int wsum[32];
    int tid = threadIdx.x, lane = tid & 31, w = tid >> 5;
    int i = blockIdx.x * 1024 + tid;
    int v = (i < M_CNT) ? g_cnt[i] : 0;
    int incl = v;
    #pragma unroll
    for (int o = 1; o < 32; o <<= 1) {
        int t = __shfl_up_sync(0xffffffffu, incl, o);
        if (lane >= o) incl += t;
    }
    if (lane == 31) wsum[w] = incl;
    __syncthreads();
    if (w == 0) {
        int s0 = wsum[lane];
        int si = s0;
        #pragma unroll
        for (int o = 1; o < 32; o <<= 1) {
            int t = __shfl_up_sync(0xffffffffu, si, o);
            if (lane >= o) si += t;
        }
        wsum[lane] = si - s0;   // exclusive warp base
    }
    __syncthreads();
    int excl = wsum[w] + incl - v;
    if (i <= M_CNT) g_off[i] = excl;
    if (tid == 1023) g_bsum[blockIdx.x] = wsum[31] + incl;  // block total
}

// ---------------- scan phase B: scan the 40 block totals (exclusive) ----------------
__global__ void scanB_kernel() {
    __shared__ int sh[2];
    int tid = threadIdx.x, lane = tid & 31, w = tid >> 5;   // 64 threads
    int v = (tid < SCAN_BLKS) ? g_bsum[tid] : 0;
    int incl = v;
    #pragma unroll
    for (int o = 1; o < 32; o <<= 1) {
        int t = __shfl_up_sync(0xffffffffu, incl, o);
        if (lane >= o) incl += t;
    }
    if (lane == 31) sh[w] = incl;
    __syncthreads();
    int base = (w == 1) ? sh[0] : 0;
    if (tid <= SCAN_BLKS) g_bbase[tid] = base + incl - v;   // exclusive
}

__device__ __forceinline__ int final_off(int i) {
    return g_off[i] + g_bbase[i >> 10];
}

// ---------------- fill CSR ----------------
__global__ void fill_kernel(const int* __restrict__ perms,
                            const int* __restrict__ edge_index,
                            const int* __restrict__ edge_type) {
    int i = blockIdx.x * blockDim.x + threadIdx.x;
    if (i >= NS * PP) return;
    int s = i / PP;
    int e = perms[i];
    int src = edge_index[e];
    int dst = edge_index[EE + e];
    int et  = edge_type[e];
    int idx = dst * NS + s;
    int pos = atomicAdd(&g_cur[idx], 1);
    g_csr[final_off(idx) + pos] = src | (et << 16);
}

// ---------------- mega kernel: one block per node ----------------
__global__ __launch_bounds__(128) void mega_kernel(
    const float* __restrict__ x,
    const float* __restrict__ rel,
    const float* __restrict__ W_B,
    const float* __restrict__ W_C,
    const float* __restrict__ b_delta,
    const float* __restrict__ b_g,
    const float* __restrict__ b_out,
    const float* __restrict__ ln_g,
    const float* __restrict__ ln_b,
    float* __restrict__ out)
{
    int n = blockIdx.x;
    int d = threadIdx.x;                  // channel, 0..127
    int lane = d & 31, warp = d >> 5;

    __shared__ __align__(16) float tok[S][D];
    __shared__ float BC[2][S][KK];        // [0]=B, [1]=C per (s,k)
    __shared__ float part[2][KK][4][S];
    __shared__ __align__(16) float scn[D];
    __shared__ float rs1[4], rs2[4];

    // ---- token 0 = x[n], tokens 1..4 = gather-mean over CSR edges ----
    float xv = x[n * D + d];
    tok[0][d] = xv;
    #pragma unroll
    for (int s = 0; s < NS; s++) {
        int idx = n * NS + s;
        int b = final_off(idx), e2 = final_off(idx + 1);
        float a0 = 0.f, a1 = 0.f, a2 = 0.f, a3 = 0.f;
        int t = b;
        // 4-way unrolled: 8 independent 128B loads per warp in flight
        for (; t + 4 <= e2; t += 4) {
            int p0 = g_csr[t], p1 = g_csr[t + 1];
            int p2 = g_csr[t + 2], p3 = g_csr[t + 3];
            a0 += x[(p0 & 0xFFFF) * D + d] + rel[(p0 >> 16) * D + d];
            a1 += x[(p1 & 0xFFFF) * D + d] + rel[(p1 >> 16) * D + d];
            a2 += x[(p2 & 0xFFFF) * D + d] + rel[(p2 >> 16) * D + d];
            a3 += x[(p3 & 0xFFFF) * D + d] + rel[(p3 >> 16) * D + d];
        }
        for (; t < e2; t++) {
            int pk = g_csr[t];
            a0 += x[(pk & 0xFFFF) * D + d] + rel[(pk >> 16) * D + d];
        }
        float acc = (a0 + a1) + (a2 + a3);
        int cnt = e2 - b;
        tok[1 + s][d] = acc / (float)(cnt > 1 ? cnt : 1);
    }
    __syncthreads();

    // ---- delta GEMV: dl[s] = softplus(tok[s] . Wdelta[:,d] + b_delta[d]) ----
    float dl[S];
    {
        float bd = b_delta[d];
        float acc[S];
        #pragma unroll
        for (int s = 0; s < S; s++) acc[s] = bd;
        const float4* wrow = (const float4*)(g_WdT + d * D);
        #pragma unroll 8
        for (int j4 = 0; j4 < 32; j4++) {
            float4 w = wrow[j4];
            #pragma unroll
            for (int s = 0; s < S; s++) {
                float4 t4 = *(const float4*)&tok[s][4 * j4];
                acc[s] += t4.x * w.x + t4.y * w.y + t4.z * w.z + t4.w * w.w;
            }
        }
        #pragma unroll
        for (int s = 0; s < S; s++) dl[s] = softplus_f(acc[s]);
    }

    // ---- B/C GEMVs: 128 threads -> (mat:2, k:16, q:4 quarter of j-range) ----
    {
        int mat = d >> 6;
        int k   = (d >> 2) & 15;
        int q   = d & 3;
        const float* W = mat ? W_C : W_B;
        float acc[S] = {0.f, 0.f, 0.f, 0.f, 0.f};
        int j0 = q * 32;
        for (int j = j0; j < j0 + 32; j++) {
            float w = W[j * KK + k];
            #pragma unroll
            for (int s = 0; s < S; s++) acc[s] += tok[s][j] * w;
        }
        #pragma unroll
        for (int s = 0; s < S; s++) part[mat][k][q][s] = acc[s];
    }
    __syncthreads();
    if (d < 2 * KK) {
        int mat = d >> 4, k = d & 15;
        #pragma unroll
        for (int s = 0; s < S; s++)
            BC[mat][s][k] = part[mat][k][0][s] + part[mat][k][1][s]
                          + part[mat][k][2][s] + part[mat][k][3][s];
    }
    __syncthreads();

    // ---- bidirectional selective scan (per-thread channel d) ----
    float A[KK];
    {
        const float4* ar = (const float4*)(g_Acont + d * KK);
        #pragma unroll
        for (int k4 = 0; k4 < 4; k4++) {
            float4 a4 = ar[k4];
            A[4 * k4 + 0] = a4.x; A[4 * k4 + 1] = a4.y;
            A[4 * k4 + 2] = a4.z; A[4 * k4 + 3] = a4.w;
        }
    }
    float xtok[S];
    #pragma unroll
    for (int s = 0; s < S; s++) xtok[s] = tok[s][d];

    float ysum = 0.f;
    {   // forward
        float st[KK];
        #pragma unroll
        for (int k = 0; k < KK; k++) st[k] = 0.f;
        #pragma unroll
        for (int s = 0; s < S; s++) {
            float dls = dl[s];
            float dx  = dls * xtok[s];
            #pragma unroll
            for (int k = 0; k < KK; k++) {
                float a = __expf(dls * A[k]);
                st[k] = a * st[k] + dx * BC[0][s][k];
                ysum += st[k] * BC[1][s][k];
            }
        }
    }
    {   // backward (reversed token order; per-token params identical)
        float st[KK];
        #pragma unroll
        for (int k = 0; k < KK; k++) st[k] = 0.f;
        #pragma unroll
        for (int s = S - 1; s >= 0; s--) {
            float dls = dl[s];
            float dx  = dls * xtok[s];
            #pragma unroll
            for (int k = 0; k < KK; k++) {
                float a = __expf(dls * A[k]);
                st[k] = a * st[k] + dx * BC[0][s][k];
                ysum += st[k] * BC[1][s][k];
            }
        }
    }
    scn[d] = ysum * (1.f / (float)S);
    __syncthreads();

    // ---- gate & out GEMVs + residual ----
    float ga = b_g[d], oa = b_out[d];
    {
        const float4* wg = (const float4*)(g_WgT + d * D);
        const float4* wo = (const float4*)(g_WoT + d * D);
        #pragma unroll 8
        for (int j4 = 0; j4 < 32; j4++) {
            float4 g4 = wg[j4];
            float4 o4 = wo[j4];
            float4 x4 = *(const float4*)&tok[0][4 * j4];
            float4 s4 = *(const float4*)&scn[4 * j4];
            ga += x4.x * g4.x + x4.y * g4.y + x4.z * g4.z + x4.w * g4.w;
            oa += s4.x * o4.x + s4.y * o4.y + s4.z * o4.z + s4.w * o4.w;
        }
    }
    float gate = ga / (1.f + __expf(-ga));   // silu
    float res  = xv + gate * oa;

    // ---- layernorm over the 128 channels ----
    float s1 = res, s2 = res * res;
    #pragma unroll
    for (int o = 16; o > 0; o >>= 1) {
        s1 += __shfl_xor_sync(0xffffffffu, s1, o);
        s2 += __shfl_xor_sync(0xffffffffu, s2, o);
    }
    if (lane == 0) { rs1[warp] = s1; rs2[warp] = s2; }
    __syncthreads();
    float t1 = rs1[0] + rs1[1] + rs1[2] + rs1[3];
    float t2 = rs2[0] + rs2[1] + rs2[2] + rs2[3];
    float mu  = t1 * (1.f / (float)D);
    float var = t2 * (1.f / (float)D) - mu * mu;
    float inv = rsqrtf(var + LN_EPS);
    out[n * D + d] = (res - mu) * inv * ln_g[d] + ln_b[d];
}

// ---------------- launch ----------------
extern "C" void kernel_launch(void* const* d_in, const int* in_sizes, int n_in,
                              void* d_out, int out_size) {
    const float* x         = (const float*)d_in[0];
    const int*   edge_index= (const int*)  d_in[1];
    const int*   edge_type = (const int*)  d_in[2];
    const int*   perms     = (const int*)  d_in[3];
    const float* rel       = (const float*)d_in[4];
    const float* logA      = (const float*)d_in[5];
    const float* W_B       = (const float*)d_in[6];
    const float* W_C       = (const float*)d_in[7];
    const float* W_delta   = (const float*)d_in[8];
    const float* b_delta   = (const float*)d_in[9];
    const float* W_g       = (const float*)d_in[10];
    const float* b_g       = (const float*)d_in[11];
    const float* W_out     = (const float*)d_in[12];
    const float* b_out     = (const float*)d_in[13];
    const float* ln_g      = (const float*)d_in[14];
    const float* ln_b      = (const float*)d_in[15];
    float* out = (float*)d_out;

    prep_zero_kernel<<<(M_CNT + 255) / 256, 256>>>(W_delta, W_g, W_out, logA);
    count_kernel<<<(NS * PP + 255) / 256, 256>>>(perms, edge_index);
    scanA_kernel<<<SCAN_BLKS, 1024>>>();
    scanB_kernel<<<1, 64>>>();
    fill_kernel<<<(NS * PP + 255) / 256, 256>>>(perms, edge_index, edge_type);
    mega_kernel<<<NN, 128>>>(x, rel, W_B, W_C, b_delta, b_g, b_out,
                             ln_g, ln_b, out);
}

// round 6
// speedup vs baseline: 1.6393x; 1.6000x over previous
#include <cuda_runtime.h>
#include <cuda_bf16.h>

#define NN 10000   // nodes
#define D  128     // d_model
#define KK 16      // d_state
#define S  5       // seq len
#define NS 4       // S-1
#define EE 320000  // edges
#define PP 80000   // edges per step
#define LN_EPS 1e-5f
#define M_CNT (NN * NS)          // 40000 counters
#define SCAN_BLKS 40             // ceil(40001 / 1024)

// ---------------- device scratch (static, no allocation) ----------------
__device__ float g_Acont[D * KK];   // -exp(log_A)
__device__ int   g_cnt[M_CNT];
__device__ int   g_off[M_CNT + 1];  // within-scan-block exclusive prefix
__device__ int   g_bsum[SCAN_BLKS];
__device__ int   g_bbase[SCAN_BLKS + 1];
__device__ int   g_cur[M_CNT];
__device__ int   g_csr[EE];         // packed: src | (etype<<16)

// ---------------- helpers ----------------
__device__ __forceinline__ float softplus_f(float v) {
    return (v > 20.f) ? v : log1pf(__expf(v));
}

// ---------------- prep: A_cont + zero counters ----------------
__global__ void prep_zero_kernel(const float* __restrict__ logA) {
    int i = blockIdx.x * blockDim.x + threadIdx.x;
    if (i < D * KK) g_Acont[i] = -expf(logA[i]);
    if (i < M_CNT) { g_cnt[i] = 0; g_cur[i] = 0; }
}

// ---------------- count edges per (dst, step) ----------------
__global__ void count_kernel(const int* __restrict__ perms,
                             const int* __restrict__ edge_index) {
    int i = blockIdx.x * blockDim.x + threadIdx.x;
    if (i >= NS * PP) return;
    int s = i / PP;
    int e = perms[i];
    int dst = edge_index[EE + e];
    atomicAdd(&g_cnt[dst * NS + s], 1);
}

// ---------------- hierarchical scan, phase A ----------------
__global__ __launch_bounds__(1024) void scanA_kernel() {
    __shared__ int wsum[32];
    int tid = threadIdx.x, lane = tid & 31, w = tid >> 5;
    int i = blockIdx.x * 1024 + tid;
    int v = (i < M_CNT) ? g_cnt[i] : 0;
    int incl = v;
    #pragma unroll
    for (int o = 1; o < 32; o <<= 1) {
        int t = __shfl_up_sync(0xffffffffu, incl, o);
        if (lane >= o) incl += t;
    }
    if (lane == 31) wsum[w] = incl;
    __syncthreads();
    if (w == 0) {
        int s0 = wsum[lane];
        int si = s0;
        #pragma unroll
        for (int o = 1; o < 32; o <<= 1) {
            int t = __shfl_up_sync(0xffffffffu, si, o);
            if (lane >= o) si += t;
        }
        wsum[lane] = si - s0;
    }
    __syncthreads();
    int excl = wsum[w] + incl - v;
    if (i <= M_CNT) g_off[i] = excl;
    if (tid == 1023) g_bsum[blockIdx.x] = wsum[31] + incl;
}

// ---------------- scan phase B ----------------
__global__ void scanB_kernel() {
    __shared__ int sh[2];
    int tid = threadIdx.x, lane = tid & 31, w = tid >> 5;   // 64 threads
    int v = (tid < SCAN_BLKS) ? g_bsum[tid] : 0;
    int incl = v;
    #pragma unroll
    for (int o = 1; o < 32; o <<= 1) {
        int t = __shfl_up_sync(0xffffffffu, incl, o);
        if (lane >= o) incl += t;
    }
    if (lane == 31) sh[w] = incl;
    __syncthreads();
    int base = (w == 1) ? sh[0] : 0;
    if (tid <= SCAN_BLKS) g_bbase[tid] = base + incl - v;
}

__device__ __forceinline__ int final_off(int i) {
    return g_off[i] + g_bbase[i >> 10];
}

// ---------------- fill CSR ----------------
__global__ void fill_kernel(const int* __restrict__ perms,
                            const int* __restrict__ edge_index,
                            const int* __restrict__ edge_type) {
    int i = blockIdx.x * blockDim.x + threadIdx.x;
    if (i >= NS * PP) return;
    int s = i / PP;
    int e = perms[i];
    int src = edge_index[e];
    int dst = edge_index[EE + e];
    int et  = edge_type[e];
    int idx = dst * NS + s;
    int pos = atomicAdd(&g_cur[idx], 1);
    g_csr[final_off(idx) + pos] = src | (et << 16);
}

// ---------------- mega kernel: one block per node ----------------
// All weight GEMVs read the ORIGINAL row-major layout W[j*D + d]; lanes at
// consecutive d -> 1 L1tex wavefront per load (coalesced), weights L1-resident.
__global__ __launch_bounds__(128) void mega_kernel(
    const float* __restrict__ x,
    const float* __restrict__ rel,
    const float* __restrict__ W_B,
    const float* __restrict__ W_C,
    const float* __restrict__ W_delta,
    const float* __restrict__ b_delta,
    const float* __restrict__ W_g,
    const float* __restrict__ b_g,
    const float* __restrict__ W_out,
    const float* __restrict__ b_out,
    const float* __restrict__ ln_g,
    const float* __restrict__ ln_b,
    float* __restrict__ out)
{
    int n = blockIdx.x;
    int d = threadIdx.x;                  // channel, 0..127
    int lane = d & 31, warp = d >> 5;

    __shared__ __align__(16) float tok[S][D];
    __shared__ float BC[2][S][KK];        // [0]=B, [1]=C per (s,k)
    __shared__ float part[2][KK][4][S];
    __shared__ __align__(16) float scn[D];
    __shared__ float rs1[4], rs2[4];

    // ---- token 0 = x[n], tokens 1..4 = gather-mean over CSR edges ----
    float xv = x[n * D + d];
    tok[0][d] = xv;
    #pragma unroll
    for (int s = 0; s < NS; s++) {
        int idx = n * NS + s;
        int b = final_off(idx), e2 = final_off(idx + 1);
        float a0 = 0.f, a1 = 0.f, a2 = 0.f, a3 = 0.f;
        int t = b;
        for (; t + 4 <= e2; t += 4) {
            int p0 = g_csr[t], p1 = g_csr[t + 1];
            int p2 = g_csr[t + 2], p3 = g_csr[t + 3];
            a0 += x[(p0 & 0xFFFF) * D + d] + rel[(p0 >> 16) * D + d];
            a1 += x[(p1 & 0xFFFF) * D + d] + rel[(p1 >> 16) * D + d];
            a2 += x[(p2 & 0xFFFF) * D + d] + rel[(p2 >> 16) * D + d];
            a3 += x[(p3 & 0xFFFF) * D + d] + rel[(p3 >> 16) * D + d];
        }
        for (; t < e2; t++) {
            int pk = g_csr[t];
            a0 += x[(pk & 0xFFFF) * D + d] + rel[(pk >> 16) * D + d];
        }
        float acc = (a0 + a1) + (a2 + a3);
        int cnt = e2 - b;
        tok[1 + s][d] = acc / (float)(cnt > 1 ? cnt : 1);
    }
    __syncthreads();

    // ---- delta GEMV (coalesced): dl[s] = softplus(sum_j tok[s][j]*Wd[j][d] + bd) ----
    float dl[S];
    {
        float bd = b_delta[d];
        float acc[S];
        #pragma unroll
        for (int s = 0; s < S; s++) acc[s] = bd;
        #pragma unroll 4
        for (int j = 0; j < D; j += 4) {
            float w0 = W_delta[(j + 0) * D + d];
            float w1 = W_delta[(j + 1) * D + d];
            float w2 = W_delta[(j + 2) * D + d];
            float w3 = W_delta[(j + 3) * D + d];
            #pragma unroll
            for (int s = 0; s < S; s++) {
                float4 t4 = *(const float4*)&tok[s][j];
                acc[s] += t4.x * w0 + t4.y * w1 + t4.z * w2 + t4.w * w3;
            }
        }
        #pragma unroll
        for (int s = 0; s < S; s++) dl[s] = softplus_f(acc[s]);
    }

    // ---- B/C GEMVs: 128 threads -> (mat:2, k:16, q:4 quarter of j-range) ----
    {
        int mat = d >> 6;
        int k   = (d >> 2) & 15;
        int q   = d & 3;
        const float* W = mat ? W_C : W_B;
        float acc[S] = {0.f, 0.f, 0.f, 0.f, 0.f};
        int j0 = q * 32;
        for (int j = j0; j < j0 + 32; j++) {
            float w = W[j * KK + k];
            #pragma unroll
            for (int s = 0; s < S; s++) acc[s] += tok[s][j] * w;
        }
        #pragma unroll
        for (int s = 0; s < S; s++) part[mat][k][q][s] = acc[s];
    }
    __syncthreads();
    if (d < 2 * KK) {
        int mat = d >> 4, k = d & 15;
        #pragma unroll
        for (int s = 0; s < S; s++)
            BC[mat][s][k] = part[mat][k][0][s] + part[mat][k][1][s]
                          + part[mat][k][2][s] + part[mat][k][3][s];
    }
    __syncthreads();

    // ---- bidirectional selective scan (per-thread channel d) ----
    float A[KK];
    {
        const float4* ar = (const float4*)(g_Acont + d * KK);
        #pragma unroll
        for (int k4 = 0; k4 < 4; k4++) {
            float4 a4 = ar[k4];
            A[4 * k4 + 0] = a4.x; A[4 * k4 + 1] = a4.y;
            A[4 * k4 + 2] = a4.z; A[4 * k4 + 3] = a4.w;
        }
    }
    float xtok[S];
    #pragma unroll
    for (int s = 0; s < S; s++) xtok[s] = tok[s][d];

    float ysum = 0.f;
    {   // forward
        float st[KK];
        #pragma unroll
        for (int k = 0; k < KK; k++) st[k] = 0.f;
        #pragma unroll
        for (int s = 0; s < S; s++) {
            float dls = dl[s];
            float dx  = dls * xtok[s];
            #pragma unroll
            for (int k = 0; k < KK; k++) {
                float a = __expf(dls * A[k]);
                st[k] = a * st[k] + dx * BC[0][s][k];
                ysum += st[k] * BC[1][s][k];
            }
        }
    }
    {   // backward
        float st[KK];
        #pragma unroll
        for (int k = 0; k < KK; k++) st[k] = 0.f;
        #pragma unroll
        for (int s = S - 1; s >= 0; s--) {
            float dls = dl[s];
            float dx  = dls * xtok[s];
            #pragma unroll
            for (int k = 0; k < KK; k++) {
                float a = __expf(dls * A[k]);
                st[k] = a * st[k] + dx * BC[0][s][k];
                ysum += st[k] * BC[1][s][k];
            }
        }
    }
    scn[d] = ysum * (1.f / (float)S);
    __syncthreads();

    // ---- gate & out GEMVs (coalesced) + residual ----
    float ga = b_g[d], oa = b_out[d];
    {
        #pragma unroll 4
        for (int j = 0; j < D; j += 4) {
            float4 x4 = *(const float4*)&tok[0][j];
            float4 s4 = *(const float4*)&scn[j];
            ga += x4.x * W_g[(j + 0) * D + d] + x4.y * W_g[(j + 1) * D + d]
                + x4.z * W_g[(j + 2) * D + d] + x4.w * W_g[(j + 3) * D + d];
            oa += s4.x * W_out[(j + 0) * D + d] + s4.y * W_out[(j + 1) * D + d]
                + s4.z * W_out[(j + 2) * D + d] + s4.w * W_out[(j + 3) * D + d];
        }
    }
    float gate = ga / (1.f + __expf(-ga));   // silu
    float res  = xv + gate * oa;

    // ---- layernorm over the 128 channels ----
    float s1 = res, s2 = res * res;
    #pragma unroll
    for (int o = 16; o > 0; o >>= 1) {
        s1 += __shfl_xor_sync(0xffffffffu, s1, o);
        s2 += __shfl_xor_sync(0xffffffffu, s2, o);
    }
    if (lane == 0) { rs1[warp] = s1; rs2[warp] = s2; }
    __syncthreads();
    float t1 = rs1[0] + rs1[1] + rs1[2] + rs1[3];
    float t2 = rs2[0] + rs2[1] + rs2[2] + rs2[3];
    float mu  = t1 * (1.f / (float)D);
    float var = t2 * (1.f / (float)D) - mu * mu;
    float inv = rsqrtf(var + LN_EPS);
    out[n * D + d] = (res - mu) * inv * ln_g[d] + ln_b[d];
}

// ---------------- launch ----------------
extern "C" void kernel_launch(void* const* d_in, const int* in_sizes, int n_in,
                              void* d_out, int out_size) {
    const float* x         = (const float*)d_in[0];
    const int*   edge_index= (const int*)  d_in[1];
    const int*   edge_type = (const int*)  d_in[2];
    const int*   perms     = (const int*)  d_in[3];
    const float* rel       = (const float*)d_in[4];
    const float* logA      = (const float*)d_in[5];
    const float* W_B       = (const float*)d_in[6];
    const float* W_C       = (const float*)d_in[7];
    const float* W_delta   = (const float*)d_in[8];
    const float* b_delta   = (const float*)d_in[9];
    const float* W_g       = (const float*)d_in[10];
    const float* b_g       = (const float*)d_in[11];
    const float* W_out     = (const float*)d_in[12];
    const float* b_out     = (const float*)d_in[13];
    const float* ln_g      = (const float*)d_in[14];
    const float* ln_b      = (const float*)d_in[15];
    float* out = (float*)d_out;

    prep_zero_kernel<<<(M_CNT + 255) / 256, 256>>>(logA);
    count_kernel<<<(NS * PP + 255) / 256, 256>>>(perms, edge_index);
    scanA_kernel<<<SCAN_BLKS, 1024>>>();
    scanB_kernel<<<1, 64>>>();
    fill_kernel<<<(NS * PP + 255) / 256, 256>>>(perms, edge_index, edge_type);
    mega_kernel<<<NN, 128>>>(x, rel, W_B, W_C, W_delta, b_delta,
                             W_g, b_g, W_out, b_out, ln_g, ln_b, out);
}